// round 7
// baseline (speedup 1.0000x reference)
#include <cuda_runtime.h>
#include <cstddef>
#include <cstdint>

#define NBATCH 32
#define SEQT   2048
#define DIN    256
#define HID    256
#define GDIM   1024   // 4*HID

// ---------------- scratch (static device allocations, allowed) ----------------
__device__ float g_xg_f[(size_t)NBATCH * SEQT * GDIM];   // 256 MB
__device__ float g_xg_r[(size_t)NBATCH * SEQT * GDIM];   // 256 MB
__device__ float g_h0 [(size_t)NBATCH * SEQT * 2 * HID]; // 128 MB

// ---------------- helpers ----------------
__device__ __forceinline__ unsigned long long pack2(float x) {
    unsigned long long r;
    asm("mov.b64 %0, {%1, %1};" : "=l"(r) : "f"(x));
    return r;
}
__device__ __forceinline__ unsigned long long pack2f(float x, float y) {
    unsigned long long r;
    asm("mov.b64 %0, {%1, %2};" : "=l"(r) : "f"(x), "f"(y));
    return r;
}
__device__ __forceinline__ void ffma2(unsigned long long& d,
                                      unsigned long long a, unsigned long long b) {
    asm("fma.rn.f32x2 %0, %1, %2, %0;" : "+l"(d) : "l"(a), "l"(b));
}
__device__ __forceinline__ float tanh_fast(float x) {
    float y;
    asm("tanh.approx.f32 %0, %1;" : "=f"(y) : "f"(x));
    return y;
}
__device__ __forceinline__ float sigm(float x) {
    return 0.5f + 0.5f * tanh_fast(0.5f * x);
}
__device__ __forceinline__ uint32_t f2tf32(float x) {
    uint32_t r;
    asm("cvt.rna.tf32.f32 %0, %1;" : "=r"(r) : "f"(x));
    return r;
}
__device__ __forceinline__ void mma_tf32(float* d, const uint32_t* a, const uint32_t* b) {
    asm("mma.sync.aligned.m16n8k8.row.col.f32.tf32.tf32.f32 "
        "{%0,%1,%2,%3}, {%4,%5,%6,%7}, {%8,%9}, {%0,%1,%2,%3};"
        : "+f"(d[0]), "+f"(d[1]), "+f"(d[2]), "+f"(d[3])
        : "r"(a[0]), "r"(a[1]), "r"(a[2]), "r"(a[3]), "r"(b[0]), "r"(b[1]));
}
__device__ __forceinline__ void cp_async16(uint32_t dst, const void* src) {
    asm volatile("cp.async.cg.shared.global [%0], [%1], 16;\n"
                 :: "r"(dst), "l"(src));
}

// =====================================================================
// tf32 tensor-core GEMM (unchanged from R4): C = A @ W^T + bias
// =====================================================================
#define GSTG 3
#define GBUF (128 * 32)   // floats per operand per stage

__global__ __launch_bounds__(256, 2)
void tf32gemm_bias(const float* __restrict__ A, const float* __restrict__ W,
                   const float* __restrict__ bias, float* __restrict__ C, int K)
{
    extern __shared__ float gsm[];
    float* sA = gsm;                 // [GSTG][128*32]
    float* sB = gsm + GSTG * GBUF;   // [GSTG][128*32]

    const int tid  = threadIdx.x;
    const int lane = tid & 31;
    const int warp = tid >> 5;
    const int wm   = warp & 1;
    const int wn   = warp >> 1;
    const size_t m0 = (size_t)blockIdx.y * 128;
    const size_t n0 = (size_t)blockIdx.x * 128;
    const int N  = gridDim.x * 128;

    const int r = lane >> 2;
    const int c = lane & 3;

    const int grow = tid >> 1;
    const int ghalf = tid & 1;

    const uint32_t sA_u32 = (uint32_t)__cvta_generic_to_shared(sA);
    const uint32_t sB_u32 = (uint32_t)__cvta_generic_to_shared(sB);

    const float* Ag = A + (m0 + grow) * (size_t)K + ghalf * 16;
    const float* Wg = W + (n0 + grow) * (size_t)K + ghalf * 16;

    const int nst = K >> 5;

    auto load_stage = [&](int ks, int s) {
        const uint32_t baseA = sA_u32 + (uint32_t)(s * GBUF + grow * 32) * 4;
        const uint32_t baseB = sB_u32 + (uint32_t)(s * GBUF + grow * 32) * 4;
        const float* ga = Ag + (size_t)ks * 32;
        const float* gw = Wg + (size_t)ks * 32;
        const int rs = grow & 7;
        #pragma unroll
        for (int j = 0; j < 4; j++) {
            const int q = ghalf * 4 + j;
            const uint32_t off = (uint32_t)((q ^ rs) << 4);
            cp_async16(baseA + off, ga + j * 4);
            cp_async16(baseB + off, gw + j * 4);
        }
    };

    float acc[4][4][4];
    #pragma unroll
    for (int mi = 0; mi < 4; mi++)
        #pragma unroll
        for (int nj = 0; nj < 4; nj++)
            #pragma unroll
            for (int q = 0; q < 4; q++) acc[mi][nj][q] = 0.f;

    load_stage(0, 0);
    asm volatile("cp.async.commit_group;" ::: "memory");
    load_stage(1, 1);
    asm volatile("cp.async.commit_group;" ::: "memory");

    #pragma unroll 1
    for (int ks = 0; ks < nst; ks++) {
        asm volatile("cp.async.wait_group 1;" ::: "memory");
        __syncthreads();

        if (ks + 2 < nst) load_stage(ks + 2, (ks + 2) % GSTG);
        asm volatile("cp.async.commit_group;" ::: "memory");

        const float* bufA = sA + (ks % GSTG) * GBUF;
        const float* bufB = sB + (ks % GSTG) * GBUF;

        #pragma unroll
        for (int slab = 0; slab < 32; slab += 8) {
            const int ch0 = ((slab >> 2) ^ r) << 2;
            const int ch1 = (((slab >> 2) + 1) ^ r) << 2;
            uint32_t af[4][4];
            #pragma unroll
            for (int mi = 0; mi < 4; mi++) {
                const int m = wm * 64 + mi * 16 + r;
                const int b0 = m * 32 + c;
                const int b8 = (m + 8) * 32 + c;
                af[mi][0] = f2tf32(bufA[b0 + ch0]);
                af[mi][1] = f2tf32(bufA[b8 + ch0]);
                af[mi][2] = f2tf32(bufA[b0 + ch1]);
                af[mi][3] = f2tf32(bufA[b8 + ch1]);
            }
            uint32_t bf[4][2];
            #pragma unroll
            for (int nj = 0; nj < 4; nj++) {
                const int n = wn * 32 + nj * 8 + r;
                const int bb = n * 32 + c;
                bf[nj][0] = f2tf32(bufB[bb + ch0]);
                bf[nj][1] = f2tf32(bufB[bb + ch1]);
            }
            #pragma unroll
            for (int mi = 0; mi < 4; mi++)
                #pragma unroll
                for (int nj = 0; nj < 4; nj++)
                    mma_tf32(acc[mi][nj], af[mi], bf[nj]);
        }
        __syncthreads();
    }

    #pragma unroll
    for (int mi = 0; mi < 4; mi++) {
        const size_t row = m0 + (size_t)(wm * 64 + mi * 16 + r);
        #pragma unroll
        for (int nj = 0; nj < 4; nj++) {
            const size_t col = n0 + (size_t)(wn * 32 + nj * 8 + c * 2);
            const float2 bz = *(const float2*)&bias[col];
            float2 v0, v1;
            v0.x = acc[mi][nj][0] + bz.x;
            v0.y = acc[mi][nj][1] + bz.y;
            v1.x = acc[mi][nj][2] + bz.x;
            v1.y = acc[mi][nj][3] + bz.y;
            *(float2*)&C[row * (size_t)N + col]       = v0;
            *(float2*)&C[(row + 8) * (size_t)N + col] = v1;
        }
    }
}
#define GEMM_SMEM (GSTG * GBUF * 2 * 4)   // 98304 B

// =====================================================================
// Persistent cluster LSTM scan v4: dataflow flags instead of cluster
// barrier. Warp kc consumes only hidden-slice kc (produced by rank kc),
// gated by a per-source monotonic flag (release-store / acquire-load).
// Double-buffered h AND partials; warps 4-7 run one step ahead of the
// epilogue warps (0-3), overlapping GEMV(t+1) with epilogue(t).
// =====================================================================
#define CLS 8
#define HSL 32
#define BGR 4
// hb[2][BGR][HID] + part[2][8][BGR][128] + flags[8]
#define HB_F     (2 * BGR * HID)
#define PART_F   (2 * 8 * BGR * 128)
#define FLAGS_F  (HB_F + PART_F)
#define LSTM_SMEM ((FLAGS_F + 8) * 4)   // 40992 B

__global__ void __cluster_dims__(CLS, 1, 1) __launch_bounds__(256, 1)
lstm_scan(const float* __restrict__ xg_f, const float* __restrict__ xg_r,
          const float* __restrict__ Whh_f, const float* __restrict__ Whh_r,
          float* __restrict__ out)
{
    extern __shared__ float sm[];
    float* hb   = sm;                  // [2][BGR][HID]
    float* part = sm + HB_F;           // [2][8][BGR][128]
    uint32_t* flags = (uint32_t*)(sm + FLAGS_F);   // [8] steps-completed per source

    const int tid   = threadIdx.x;
    const int slice = blockIdx.x & 7;        // cluster rank
    const int cid   = blockIdx.x >> 3;
    const int dir   = cid & 1;
    const int bg    = cid >> 1;              // 0..7

    const float* xg  = dir ? xg_r : xg_f;
    const float* Whh = dir ? Whh_r : Whh_f;

    const int kc = tid >> 5;   // k-chunk (warp id) == source rank it consumes
    const int rg = tid & 31;   // row group: rows 4rg..4rg+3 of the slice

    // ---- load this thread's W_hh fragment into registers, pre-packed.
    unsigned long long wr[32][2];   // [local k][row pair]
    {
        const int gate = rg >> 3;
        const int j0   = 4 * (rg & 7);
        const size_t base = (size_t)gate * HID + slice * HSL + j0;
        const float* w0 = Whh + (base + 0) * HID + kc * 32;
        const float* w1 = Whh + (base + 1) * HID + kc * 32;
        const float* w2 = Whh + (base + 2) * HID + kc * 32;
        const float* w3 = Whh + (base + 3) * HID + kc * 32;
        #pragma unroll
        for (int k4 = 0; k4 < 32; k4 += 4) {
            const float4 a = *(const float4*)(w0 + k4);
            const float4 b = *(const float4*)(w1 + k4);
            const float4 c = *(const float4*)(w2 + k4);
            const float4 d = *(const float4*)(w3 + k4);
            #pragma unroll
            for (int u = 0; u < 4; u++) {
                wr[k4 + u][0] = pack2f(((const float*)&a)[u], ((const float*)&b)[u]);
                wr[k4 + u][1] = pack2f(((const float*)&c)[u], ((const float*)&d)[u]);
            }
        }
    }
    for (int i = tid; i < HB_F; i += 256) hb[i] = 0.f;
    if (tid < 8) flags[tid] = 0;
    __syncthreads();
    asm volatile("barrier.cluster.arrive.aligned;" ::: "memory");
    asm volatile("barrier.cluster.wait.aligned;" ::: "memory");

    const uint32_t smem_base = (uint32_t)__cvta_generic_to_shared(sm);
    const uint32_t faddr = smem_base + (uint32_t)(FLAGS_F + kc) * 4u;  // own flag[kc]

    const int eb = tid >> 5;   // epilogue batch (tid<128)
    const int ej = tid & 31;   // epilogue hidden j

    // precompute remote h-slot addresses (buffer 0); add buffer offset in-loop
    uint32_t hro[CLS];
    if (tid < 128) {
        const uint32_t la = smem_base
            + (uint32_t)(eb * HID + slice * HSL + ej) * 4u;
        #pragma unroll
        for (int rk = 0; rk < CLS; rk++)
            asm("mapa.shared::cluster.u32 %0, %1, %2;"
                : "=r"(hro[rk]) : "r"(la), "r"(rk));
    }
    uint32_t fro = 0;
    if (tid < 8) {
        const uint32_t la = smem_base + (uint32_t)(FLAGS_F + slice) * 4u;
        asm("mapa.shared::cluster.u32 %0, %1, %2;"
            : "=r"(fro) : "r"(la), "r"(tid));
    }

    float c_state = 0.f;

    // xg prefetch (consumed by epilogue of the same step)
    float xgi = 0.f, xgf = 0.f, xgg = 0.f, xgo = 0.f;
    const float* xbase = xg + (size_t)(bg * BGR + eb) * SEQT * GDIM
                            + slice * HSL + ej;
    if (tid < 128) {
        const int t0 = dir ? (SEQT - 1) : 0;
        const float* xp = xbase + (size_t)t0 * GDIM;
        xgi = xp[0]; xgf = xp[HID]; xgg = xp[2 * HID]; xgo = xp[3 * HID];
    }

    #pragma unroll 1
    for (int it = 0; it < SEQT; ++it) {
        const int p = it & 1;

        // ---- wait for source kc's h(it-1): flag[kc] >= it (acquire)
        uint32_t fv;
        do {
            asm volatile("ld.acquire.cluster.shared::cta.u32 %0, [%1];"
                         : "=r"(fv) : "r"(faddr) : "memory");
        } while ((int)fv < it);

        // ---- GEMV chunk kc from register weights
        unsigned long long acc2[2][4];
        #pragma unroll
        for (int rp = 0; rp < 2; rp++)
            #pragma unroll
            for (int b = 0; b < 4; b++) acc2[rp][b] = 0ull;

        const float* hbp = hb + p * (BGR * HID);
        #pragma unroll
        for (int kk = 0; kk < 32; kk += 4) {
            const int k = (kc << 5) + kk;
            const float4 h0 = *(const float4*)(hbp + 0 * HID + k);
            const float4 h1 = *(const float4*)(hbp + 1 * HID + k);
            const float4 h2 = *(const float4*)(hbp + 2 * HID + k);
            const float4 h3 = *(const float4*)(hbp + 3 * HID + k);
            #pragma unroll
            for (int u = 0; u < 4; u++) {
                const unsigned long long hd[4] = {
                    pack2(((const float*)&h0)[u]), pack2(((const float*)&h1)[u]),
                    pack2(((const float*)&h2)[u]), pack2(((const float*)&h3)[u])};
                #pragma unroll
                for (int b = 0; b < 4; b++) {
                    ffma2(acc2[0][b], wr[kk + u][0], hd[b]);
                    ffma2(acc2[1][b], wr[kk + u][1], hd[b]);
                }
            }
        }

        float* partp = part + p * (8 * BGR * 128);
        #pragma unroll
        for (int b = 0; b < 4; b++) {
            float* pp = partp + (kc * BGR + b) * 128 + (rg << 2);
            *(unsigned long long*)(pp)     = acc2[0][b];
            *(unsigned long long*)(pp + 2) = acc2[1][b];
        }
        __syncthreads();   // partials(it) ready; also fences hb/part reuse

        // ---- epilogue on warps 0-3 only; warps 4-7 loop straight to it+1
        if (tid < 128) {
            float si = xgi, sf = xgf, sg = xgg, so = xgo;
            #pragma unroll
            for (int q = 0; q < 8; q++) {
                const float* pp = partp + (q * BGR + eb) * 128 + ej;
                si += pp[0];
                sf += pp[32];
                sg += pp[64];
                so += pp[96];
            }
            const float iv = sigm(si);
            const float fv2 = sigm(sf);
            const float gv = tanh_fast(sg);
            const float ov = sigm(so);
            c_state = fv2 * c_state + iv * gv;
            const float h = ov * tanh_fast(c_state);

            // prefetch xg for next step (hidden under the next GEMV)
            const int itn = it + 1;
            if (itn < SEQT) {
                const int ttn = dir ? (SEQT - 1 - itn) : itn;
                const float* xp = xbase + (size_t)ttn * GDIM;
                xgi = xp[0]; xgf = xp[HID]; xgg = xp[2 * HID]; xgo = xp[3 * HID];
            }

            // broadcast h(it) into every rank's hb[p^1] (incl. self)
            const uint32_t boff = (uint32_t)((p ^ 1) * BGR * HID * 4);
            #pragma unroll
            for (int rk = 0; rk < CLS; rk++)
                asm volatile("st.shared::cluster.f32 [%0], %1;"
                             :: "r"(hro[rk] + boff), "f"(h));

            asm volatile("bar.sync 1, 128;" ::: "memory");  // warps 0-3 join
            if (tid < 8)
                asm volatile("st.release.cluster.shared::cluster.u32 [%0], %1;"
                             :: "r"(fro), "r"(it + 1) : "memory");

            const int tt = dir ? (SEQT - 1 - it) : it;
            out[((size_t)(bg * BGR + eb) * SEQT + tt) * (2 * HID)
                + dir * HID + slice * HSL + ej] = h;
        }
    }

    asm volatile("barrier.cluster.arrive.aligned;" ::: "memory");
    asm volatile("barrier.cluster.wait.aligned;" ::: "memory");
}

// =====================================================================
extern "C" void kernel_launch(void* const* d_in, const int* in_sizes, int n_in,
                              void* d_out, int out_size)
{
    const float* x      = (const float*)d_in[0];
    const float* Wih_f0 = (const float*)d_in[1];
    const float* Whh_f0 = (const float*)d_in[2];
    const float* b_f0   = (const float*)d_in[3];
    const float* Wih_r0 = (const float*)d_in[4];
    const float* Whh_r0 = (const float*)d_in[5];
    const float* b_r0   = (const float*)d_in[6];
    const float* Wih_f1 = (const float*)d_in[7];
    const float* Whh_f1 = (const float*)d_in[8];
    const float* b_f1   = (const float*)d_in[9];
    const float* Wih_r1 = (const float*)d_in[10];
    const float* Whh_r1 = (const float*)d_in[11];
    const float* b_r1   = (const float*)d_in[12];
    float* out = (float*)d_out;

    float *xg_f, *xg_r, *h0;
    cudaGetSymbolAddress((void**)&xg_f, g_xg_f);
    cudaGetSymbolAddress((void**)&xg_r, g_xg_r);
    cudaGetSymbolAddress((void**)&h0,  g_h0);

    cudaFuncSetAttribute(lstm_scan, cudaFuncAttributeMaxDynamicSharedMemorySize,
                         LSTM_SMEM);
    cudaFuncSetAttribute(tf32gemm_bias, cudaFuncAttributeMaxDynamicSharedMemorySize,
                         GEMM_SMEM);

    dim3 blk(256);
    dim3 grid_g(GDIM / 128, (NBATCH * SEQT) / 128);   // (8, 512)

    // layer 0: input projections + scan
    tf32gemm_bias<<<grid_g, blk, GEMM_SMEM>>>(x, Wih_f0, b_f0, xg_f, DIN);
    tf32gemm_bias<<<grid_g, blk, GEMM_SMEM>>>(x, Wih_r0, b_r0, xg_r, DIN);
    lstm_scan<<<128, blk, LSTM_SMEM>>>(xg_f, xg_r, Whh_f0, Whh_r0, h0);

    // layer 1: input projections over concat(h_f0,h_r0) + scan
    tf32gemm_bias<<<grid_g, blk, GEMM_SMEM>>>(h0, Wih_f1, b_f1, xg_f, 2 * HID);
    tf32gemm_bias<<<grid_g, blk, GEMM_SMEM>>>(h0, Wih_r1, b_r1, xg_r, 2 * HID);
    lstm_scan<<<128, blk, LSTM_SMEM>>>(xg_f, xg_r, Whh_f1, Whh_r1, out);
}